// round 1
// baseline (speedup 1.0000x reference)
#include <cuda_runtime.h>

// Raw (un-normalized) per-i losses. B is fixed at 16384 for this problem;
// sized with headroom. __device__ global scratch is allocation-guard safe.
__device__ float g_loss[65536];

__device__ __forceinline__ float warp_sum(float v) {
    #pragma unroll
    for (int off = 16; off > 0; off >>= 1)
        v += __shfl_down_sync(0xFFFFFFFFu, v, off);
    return v;
}

__global__ void __launch_bounds__(256)
triplet_kernel(const float* __restrict__ feats,
               const float* __restrict__ label,
               const int*   __restrict__ idx1,
               const int*   __restrict__ idx2,
               int B, int D) {
    const int i = blockIdx.x;

    // _fix_indices replication
    const int r1 = idx1[i];
    const int r2 = idx2[i];
    int a = (i + 1 + (r1 % (B - 1))) % B;
    int b = (i + 1 + (r2 % (B - 1))) % B;
    if (b == a) b = (i + 1 + ((r2 + 1) % (B - 1))) % B;

    const float4* __restrict__ A  = (const float4*)(feats + (size_t)i * D);
    const float4* __restrict__ T1 = (const float4*)(feats + (size_t)a * D);
    const float4* __restrict__ T2 = (const float4*)(feats + (size_t)b * D);

    const int n4 = D >> 2;  // 512 for D=2048
    float s1 = 0.f, s2 = 0.f;
    for (int j = threadIdx.x; j < n4; j += blockDim.x) {
        float4 av = A[j];
        float4 v1 = T1[j];
        float4 v2 = T2[j];
        float d;
        d = av.x - v1.x; s1 = fmaf(d, d, s1);
        d = av.y - v1.y; s1 = fmaf(d, d, s1);
        d = av.z - v1.z; s1 = fmaf(d, d, s1);
        d = av.w - v1.w; s1 = fmaf(d, d, s1);
        d = av.x - v2.x; s2 = fmaf(d, d, s2);
        d = av.y - v2.y; s2 = fmaf(d, d, s2);
        d = av.z - v2.z; s2 = fmaf(d, d, s2);
        d = av.w - v2.w; s2 = fmaf(d, d, s2);
    }

    // Block reduction (8 warps)
    __shared__ float sh1[8], sh2[8];
    s1 = warp_sum(s1);
    s2 = warp_sum(s2);
    const int lane = threadIdx.x & 31;
    const int wid  = threadIdx.x >> 5;
    if (lane == 0) { sh1[wid] = s1; sh2[wid] = s2; }
    __syncthreads();

    if (threadIdx.x == 0) {
        float t1s = 0.f, t2s = 0.f;
        #pragma unroll
        for (int w = 0; w < 8; w++) { t1s += sh1[w]; t2s += sh2[w]; }

        const float mu    = (float)136.72353790613718;
        const float sigma = (float)62.34640414043511;

        float li_raw = label[i];
        float la = label[a]; if (a < i) la = (la - mu) / sigma;  // already normalized by step a
        float lb = label[b]; if (b < i) lb = (lb - mu) / sigma;

        float ld1 = fabsf(li_raw - la);
        float ld2 = fabsf(li_raw - lb);
        bool cond = (ld1 >= ld2);

        // t1 = feats[a], t2 = feats[b]; near = cond ? t2 : t1
        float dp = cond ? t2s : t1s;   // anchor->near squared distance
        float dn = cond ? t1s : t2s;   // anchor->far  squared distance
        float near_l = cond ? lb : la;
        float far_l  = cond ? la : lb;

        float li = (li_raw - mu) / sigma;
        float nl = (near_l - mu) / sigma;  // note: may be double-normalized — matches reference
        float fl = (far_l  - mu) / sigma;

        float alpha = (li - fl) * (li - fl) - (li - nl) * (li - nl);
        float loss  = dp - dn + 0.5f * alpha;
        g_loss[i] = loss > 0.f ? loss : 0.f;
    }
}

// Deterministic fixed-order reduction of the 16384 per-i losses.
__global__ void __launch_bounds__(256)
reduce_kernel(float* __restrict__ out, int B) {
    __shared__ float sh[256];
    float s = 0.f;
    for (int j = threadIdx.x; j < B; j += 256)
        s += g_loss[j];
    sh[threadIdx.x] = s;
    __syncthreads();
    #pragma unroll
    for (int k = 128; k > 0; k >>= 1) {
        if (threadIdx.x < k) sh[threadIdx.x] += sh[threadIdx.x + k];
        __syncthreads();
    }
    if (threadIdx.x == 0) out[0] = sh[0];
}

extern "C" void kernel_launch(void* const* d_in, const int* in_sizes, int n_in,
                              void* d_out, int out_size) {
    const float* feats = (const float*)d_in[0];
    const float* label = (const float*)d_in[1];
    const int*   idx1  = (const int*)d_in[2];
    const int*   idx2  = (const int*)d_in[3];

    const int B = in_sizes[1];
    const int D = in_sizes[0] / B;

    triplet_kernel<<<B, 256>>>(feats, label, idx1, idx2, B, D);
    reduce_kernel<<<1, 256>>>((float*)d_out, B);
}